// round 4
// baseline (speedup 1.0000x reference)
#include <cuda_runtime.h>
#include <cuda_bf16.h>
#include <cstdint>

#define D 128
#define DV 32          // D / 4 (float4)
#define EPS 1e-5f
#define NT 32          // nodes per MLP block
#define PA 136         // bf16 tile pitch (272B rows -> conflict-free LDSM)
#define PS 132         // f32 h2 tile pitch
#define MAXN 50000
#define MAXE 600000

// Device scratch (allocation-free rule: __device__ globals)
__device__ float4 g_agg4[(size_t)MAXN * DV];   // aggregated messages [N][D]
__device__ float4 g_hln4[(size_t)MAXN * DV];   // post-LayerNorm h    [N][D]
__device__ float  g_colsum[D];
__device__ float  g_colsumsq[D];
__device__ float  g_mul[D];
__device__ float  g_sub[D];
__device__ int    g_cnt[MAXN];        // histogram -> placement cursors
__device__ int    g_rowstart[MAXN + 1];
__device__ int    g_csr[MAXE];        // edge ids sorted by dst
// Pre-packed weights in B-fragment register order:
// [kt(8)][nsub(16)][lane(32)] -> uint4{bhi0,bhi1,blo0,blo1}
__device__ uint4  g_w1p[4096];
__device__ uint4  g_w2p[4096];

// ---------------------------------------------------------------------------
// helpers
// ---------------------------------------------------------------------------
__device__ __forceinline__ uint32_t smem_u32(const void* p) {
    return (uint32_t)__cvta_generic_to_shared(p);
}

__device__ __forceinline__ void ldsm_x4(uint32_t* r, uint32_t addr) {
    asm volatile("ldmatrix.sync.aligned.m8n8.x4.shared.b16 {%0,%1,%2,%3}, [%4];"
                 : "=r"(r[0]), "=r"(r[1]), "=r"(r[2]), "=r"(r[3]) : "r"(addr));
}

__device__ __forceinline__ void mma16816(float* d, const uint32_t* a,
                                         const uint32_t* b) {
    asm volatile(
        "mma.sync.aligned.m16n8k16.row.col.f32.bf16.bf16.f32 "
        "{%0,%1,%2,%3}, {%4,%5,%6,%7}, {%8,%9}, {%0,%1,%2,%3};"
        : "+f"(d[0]), "+f"(d[1]), "+f"(d[2]), "+f"(d[3])
        : "r"(a[0]), "r"(a[1]), "r"(a[2]), "r"(a[3]), "r"(b[0]), "r"(b[1]));
}

__device__ __forceinline__ uint32_t bf2_hi(float a, float b, float& ra, float& rb) {
    __nv_bfloat16 ha = __float2bfloat16_rn(a);
    __nv_bfloat16 hb = __float2bfloat16_rn(b);
    ra = a - __bfloat162float(ha);
    rb = b - __bfloat162float(hb);
    __nv_bfloat162 h; h.x = ha; h.y = hb;
    return *(uint32_t*)&h;
}
__device__ __forceinline__ uint32_t bf2(float a, float b) {
    __nv_bfloat162 h; h.x = __float2bfloat16_rn(a); h.y = __float2bfloat16_rn(b);
    return *(uint32_t*)&h;
}

// ---------------------------------------------------------------------------
// K0: zero histogram + stats accumulators
// ---------------------------------------------------------------------------
__global__ void k_zero(int N) {
    int i = blockIdx.x * blockDim.x + threadIdx.x;
    if (i < N) g_cnt[i] = 0;
    if (i < D) { g_colsum[i] = 0.f; g_colsumsq[i] = 0.f; }
}

// ---------------------------------------------------------------------------
// K1a: histogram of dst
// ---------------------------------------------------------------------------
__global__ void k_hist(const int* __restrict__ ei, int E) {
    int e = blockIdx.x * blockDim.x + threadIdx.x;
    if (e < E) atomicAdd(&g_cnt[ei[E + e]], 1);
}

// ---------------------------------------------------------------------------
// K1b: single-block exclusive scan of g_cnt -> g_rowstart; g_cnt becomes cursor
// ---------------------------------------------------------------------------
__global__ void k_scan(int N, int E) {
    __shared__ int warpsum[32];
    const int t = threadIdx.x;             // 0..1023
    const int chunk = (N + 1023) >> 10;
    const int b = t * chunk;
    const int e = min(b + chunk, N);
    int s = 0;
    for (int i = b; i < e; ++i) s += g_cnt[i];
    int lane = t & 31, wid = t >> 5;
    int v = s;
    #pragma unroll
    for (int o = 1; o < 32; o <<= 1) {
        int u = __shfl_up_sync(0xFFFFFFFFu, v, o);
        if (lane >= o) v += u;
    }
    if (lane == 31) warpsum[wid] = v;
    __syncthreads();
    if (wid == 0) {
        int ws = warpsum[lane];
        #pragma unroll
        for (int o = 1; o < 32; o <<= 1) {
            int u = __shfl_up_sync(0xFFFFFFFFu, ws, o);
            if (lane >= o) ws += u;
        }
        warpsum[lane] = ws;
    }
    __syncthreads();
    int run = v - s + (wid ? warpsum[wid - 1] : 0);
    for (int i = b; i < e; ++i) {
        int c = g_cnt[i];
        g_rowstart[i] = run;
        g_cnt[i] = run;                    // placement cursor
        run += c;
    }
    if (t == 0) g_rowstart[N] = E;
}

// ---------------------------------------------------------------------------
// K1c: place edge ids into CSR order
// ---------------------------------------------------------------------------
__global__ void k_place(const int* __restrict__ ei, int E) {
    int e = blockIdx.x * blockDim.x + threadIdx.x;
    if (e < E) {
        int d = ei[E + e];
        int p = atomicAdd(&g_cnt[d], 1);
        g_csr[p] = e;
    }
}

// ---------------------------------------------------------------------------
// K1d: gather-aggregate. One warp per node; lane owns 4 channels (float4).
// ---------------------------------------------------------------------------
__global__ void k_agg(const float* __restrict__ nh,
                      const float* __restrict__ eh,
                      const int* __restrict__ ei,
                      int N) {
    int node = blockIdx.x * 8 + (threadIdx.x >> 5);
    int lane = threadIdx.x & 31;
    if (node >= N) return;
    int i   = g_rowstart[node];
    int end = g_rowstart[node + 1];
    float4 acc = make_float4(0.f, 0.f, 0.f, 0.f);
    int eid = 0, src = 0;
    if (i < end) { eid = g_csr[i]; src = ei[eid]; }
    while (i < end) {
        int in = i + 1;
        int eid_n = eid, src_n = src;
        if (in < end) { eid_n = g_csr[in]; src_n = ei[eid_n]; }
        float4 a = ((const float4*)(nh + (size_t)src * D))[lane];
        float4 b = ((const float4*)(eh + (size_t)eid * D))[lane];
        acc.x += a.x + b.x; acc.y += a.y + b.y;
        acc.z += a.z + b.z; acc.w += a.w + b.w;
        i = in; eid = eid_n; src = src_n;
    }
    g_agg4[(size_t)node * DV + lane] = acc;
}

// ---------------------------------------------------------------------------
// Kp: pack W1/W2 into bf16 hi/lo B-fragment order (4096 threads)
// ---------------------------------------------------------------------------
__global__ void k_prep(const float* __restrict__ w1, const float* __restrict__ w2) {
    int idx = blockIdx.x * blockDim.x + threadIdx.x;
    if (idx >= 4096) return;
    int lane = idx & 31;
    int nsub = (idx >> 5) & 15;
    int kt   = idx >> 9;
    int k0 = kt * 16 + (lane & 3) * 2;
    int n  = nsub * 8 + (lane >> 2);

    {
        float a0 = w1[(k0    ) * D + n], a1 = w1[(k0 + 1) * D + n];
        float a2 = w1[(k0 + 8) * D + n], a3 = w1[(k0 + 9) * D + n];
        float r0, r1, r2, r3;
        uint4 q;
        q.x = bf2_hi(a0, a1, r0, r1);
        q.y = bf2_hi(a2, a3, r2, r3);
        q.z = bf2(r0, r1);
        q.w = bf2(r2, r3);
        g_w1p[idx] = q;
    }
    {
        float a0 = w2[(k0    ) * D + n], a1 = w2[(k0 + 1) * D + n];
        float a2 = w2[(k0 + 8) * D + n], a3 = w2[(k0 + 9) * D + n];
        float r0, r1, r2, r3;
        uint4 q;
        q.x = bf2_hi(a0, a1, r0, r1);
        q.y = bf2_hi(a2, a3, r2, r3);
        q.z = bf2(r0, r1);
        q.w = bf2(r2, r3);
        g_w2p[idx] = q;
    }
}

// ---------------------------------------------------------------------------
// K2: tensor-core MLP (3-term bf16 split) + LayerNorm + GraphNorm partials.
// (unchanged from R3)
// ---------------------------------------------------------------------------
__global__ void k_mlp(const float* __restrict__ b1, const float* __restrict__ b2,
                      const float* __restrict__ lng, const float* __restrict__ lnb,
                      int N) {
    extern __shared__ char sb[];
    __nv_bfloat16* sAhi = (__nv_bfloat16*)(sb);
    float*         sS   = (float*)(sb + 34816);
    float*         sPartS = (float*)(sb);
    float*         sPartQ = (float*)(sb + 4096);

    const int t    = threadIdx.x;
    const int lane = t & 31;
    const int w    = t >> 5;
    const int nodeBase = blockIdx.x * NT;

    {
        int n  = t >> 3;
        int k0 = (t & 7) * 16;
        int gn = nodeBase + n;
        __nv_bfloat16* rowHi = sAhi + n * PA;
        #pragma unroll
        for (int i = 0; i < 4; ++i) {
            float4 v = make_float4(0.f, 0.f, 0.f, 0.f);
            if (gn < N) v = g_agg4[(size_t)gn * DV + (k0 >> 2) + i];
            int kk = k0 + i * 4;
            float rx, ry, rz, rw;
            uint32_t h0 = bf2_hi(v.x, v.y, rx, ry);
            uint32_t h1 = bf2_hi(v.z, v.w, rz, rw);
            *(uint32_t*)((char*)(rowHi + kk) )            = h0;
            *(uint32_t*)((char*)(rowHi + kk + 2))         = h1;
            *(uint32_t*)((char*)(rowHi + kk) + 8704)      = bf2(rx, ry);
            *(uint32_t*)((char*)(rowHi + kk + 2) + 8704)  = bf2(rz, rw);
        }
    }
    __syncthreads();

    const int mh = w & 1;
    const int nq = w >> 1;
    uint32_t aHi = smem_u32(sAhi + (mh * 16 + (lane & 15)) * PA) + (lane >> 4) * 16;

    float acc[16];
    #pragma unroll
    for (int i = 0; i < 16; ++i) acc[i] = 0.f;

    #pragma unroll
    for (int kt = 0; kt < 8; ++kt) {
        uint32_t ah[4], al[4];
        ldsm_x4(ah, aHi + kt * 32);
        ldsm_x4(al, aHi + 8704 + kt * 32);
        #pragma unroll
        for (int s = 0; s < 4; ++s) {
            uint4 q = g_w1p[(kt * 16 + nq * 4 + s) * 32 + lane];
            mma16816(acc + 4 * s, ah, &q.x);
            mma16816(acc + 4 * s, ah, &q.z);
            mma16816(acc + 4 * s, al, &q.x);
        }
    }
    #pragma unroll
    for (int s = 0; s < 4; ++s) {
        int cb = nq * 32 + s * 8 + (lane & 3) * 2;
        int r0 = mh * 16 + (lane >> 2);
        float2 bb = *(const float2*)(b1 + cb);
        float v00 = fmaxf(acc[4*s+0] + bb.x, 0.f);
        float v01 = fmaxf(acc[4*s+1] + bb.y, 0.f);
        float v10 = fmaxf(acc[4*s+2] + bb.x, 0.f);
        float v11 = fmaxf(acc[4*s+3] + bb.y, 0.f);
        float rx, ry;
        char* p0 = (char*)(sAhi + r0 * PA + cb) + 17408;
        char* p1 = (char*)(sAhi + (r0 + 8) * PA + cb) + 17408;
        uint32_t h;
        h = bf2_hi(v00, v01, rx, ry);
        *(uint32_t*)p0 = h; *(uint32_t*)(p0 + 8704) = bf2(rx, ry);
        h = bf2_hi(v10, v11, rx, ry);
        *(uint32_t*)p1 = h; *(uint32_t*)(p1 + 8704) = bf2(rx, ry);
    }
    __syncthreads();

    #pragma unroll
    for (int i = 0; i < 16; ++i) acc[i] = 0.f;

    #pragma unroll
    for (int kt = 0; kt < 8; ++kt) {
        uint32_t ah[4], al[4];
        ldsm_x4(ah, aHi + 17408 + kt * 32);
        ldsm_x4(al, aHi + 26112 + kt * 32);
        #pragma unroll
        for (int s = 0; s < 4; ++s) {
            uint4 q = g_w2p[(kt * 16 + nq * 4 + s) * 32 + lane];
            mma16816(acc + 4 * s, ah, &q.x);
            mma16816(acc + 4 * s, ah, &q.z);
            mma16816(acc + 4 * s, al, &q.x);
        }
    }
    #pragma unroll
    for (int s = 0; s < 4; ++s) {
        int cb = nq * 32 + s * 8 + (lane & 3) * 2;
        int r0 = mh * 16 + (lane >> 2);
        float2 bb = *(const float2*)(b2 + cb);
        *(float2*)(sS + r0 * PS + cb)       = make_float2(acc[4*s+0] + bb.x, acc[4*s+1] + bb.y);
        *(float2*)(sS + (r0 + 8) * PS + cb) = make_float2(acc[4*s+2] + bb.x, acc[4*s+3] + bb.y);
    }
    __syncthreads();

    float colS[4] = {0.f, 0.f, 0.f, 0.f};
    float colQ[4] = {0.f, 0.f, 0.f, 0.f};

    #pragma unroll
    for (int r = 0; r < 4; ++r) {
        int n  = w + r * 8;
        int gn = nodeBase + n;
        float v0 = sS[n * PS + lane];
        float v1 = sS[n * PS + lane + 32];
        float v2 = sS[n * PS + lane + 64];
        float v3 = sS[n * PS + lane + 96];
        float s = v0 + v1 + v2 + v3;
        float q = v0*v0 + v1*v1 + v2*v2 + v3*v3;
        #pragma unroll
        for (int o = 16; o; o >>= 1) {
            s += __shfl_xor_sync(0xFFFFFFFFu, s, o);
            q += __shfl_xor_sync(0xFFFFFFFFu, q, o);
        }
        float mu  = s * (1.f / 128.f);
        float var = q * (1.f / 128.f) - mu * mu;
        float inv = rsqrtf(var + EPS);
        if (gn < N) {
            float y0 = (v0 - mu) * inv * lng[lane]      + lnb[lane];
            float y1 = (v1 - mu) * inv * lng[lane + 32] + lnb[lane + 32];
            float y2 = (v2 - mu) * inv * lng[lane + 64] + lnb[lane + 64];
            float y3 = (v3 - mu) * inv * lng[lane + 96] + lnb[lane + 96];
            float* hp = (float*)(g_hln4 + (size_t)gn * DV);
            hp[lane]      = y0;
            hp[lane + 32] = y1;
            hp[lane + 64] = y2;
            hp[lane + 96] = y3;
            colS[0] += y0; colQ[0] += y0 * y0;
            colS[1] += y1; colQ[1] += y1 * y1;
            colS[2] += y2; colQ[2] += y2 * y2;
            colS[3] += y3; colQ[3] += y3 * y3;
        }
    }
    __syncthreads();
    #pragma unroll
    for (int qq = 0; qq < 4; ++qq) {
        sPartS[w * D + lane + 32 * qq] = colS[qq];
        sPartQ[w * D + lane + 32 * qq] = colQ[qq];
    }
    __syncthreads();
    if (t < D) {
        float s = 0.f, q = 0.f;
        #pragma unroll
        for (int w8 = 0; w8 < 8; ++w8) {
            s += sPartS[w8 * D + t];
            q += sPartQ[w8 * D + t];
        }
        atomicAdd(&g_colsum[t], s);
        atomicAdd(&g_colsumsq[t], q);
    }
}

// ---------------------------------------------------------------------------
// K3: finalize GraphNorm stats (1 block, 128 threads)
// ---------------------------------------------------------------------------
__global__ void k_statfin(const float* __restrict__ gnw,
                          const float* __restrict__ gnms,
                          float invN) {
    int c = threadIdx.x;
    float gmu = g_colsum[c] * invN;
    float e2  = g_colsumsq[c] * invN;
    float ms  = gnms[c];
    float gvar = e2 - 2.f * ms * gmu * gmu + ms * ms * gmu * gmu;
    g_mul[c] = rsqrtf(gvar + EPS) * gnw[c];
    g_sub[c] = ms * gmu;
}

// ---------------------------------------------------------------------------
// K4: out = relu((hln - sub) * mul + gn_b) + node_hidden
// ---------------------------------------------------------------------------
__global__ void k_final(const float* __restrict__ nh,
                        const float* __restrict__ gnb,
                        float* __restrict__ out,
                        int total4) {
    int i = blockIdx.x * blockDim.x + threadIdx.x;
    if (i >= total4) return;
    int c4 = (i & (DV - 1)) * 4;
    float4 h = g_hln4[i];
    float4 x = ((const float4*)nh)[i];
    float4 o;
    o.x = fmaxf((h.x - g_sub[c4 + 0]) * g_mul[c4 + 0] + gnb[c4 + 0], 0.f) + x.x;
    o.y = fmaxf((h.y - g_sub[c4 + 1]) * g_mul[c4 + 1] + gnb[c4 + 1], 0.f) + x.y;
    o.z = fmaxf((h.z - g_sub[c4 + 2]) * g_mul[c4 + 2] + gnb[c4 + 2], 0.f) + x.z;
    o.w = fmaxf((h.w - g_sub[c4 + 3]) * g_mul[c4 + 3] + gnb[c4 + 3], 0.f) + x.w;
    ((float4*)out)[i] = o;
}

// ---------------------------------------------------------------------------
extern "C" void kernel_launch(void* const* d_in, const int* in_sizes, int n_in,
                              void* d_out, int out_size) {
    const float* nh   = (const float*)d_in[0];
    const float* eh   = (const float*)d_in[1];
    const float* w1   = (const float*)d_in[2];
    const float* b1   = (const float*)d_in[3];
    const float* w2   = (const float*)d_in[4];
    const float* b2   = (const float*)d_in[5];
    const float* lng  = (const float*)d_in[6];
    const float* lnb  = (const float*)d_in[7];
    const float* gnw  = (const float*)d_in[8];
    const float* gnb  = (const float*)d_in[9];
    const float* gnms = (const float*)d_in[10];
    const int*   ei   = (const int*)d_in[11];

    int N = in_sizes[0] / D;
    int E = in_sizes[1] / D;
    int total4 = N * DV;

    const int SMEM_BYTES = 51712;
    cudaFuncSetAttribute(k_mlp, cudaFuncAttributeMaxDynamicSharedMemorySize, SMEM_BYTES);

    k_zero<<<(N + 255) / 256, 256>>>(N);
    k_hist<<<(E + 255) / 256, 256>>>(ei, E);
    k_scan<<<1, 1024>>>(N, E);
    k_place<<<(E + 255) / 256, 256>>>(ei, E);
    k_prep<<<16, 256>>>(w1, w2);
    k_agg<<<(N + 7) / 8, 256>>>(nh, eh, ei, N);
    k_mlp<<<(N + NT - 1) / NT, 256, SMEM_BYTES>>>(b1, b2, lng, lnb, N);
    k_statfin<<<1, 128>>>(gnw, gnms, 1.f / (float)N);
    k_final<<<(total4 + 255) / 256, 256>>>(nh, gnb, (float*)d_out, total4);
}

// round 5
// speedup vs baseline: 1.2926x; 1.2926x over previous
#include <cuda_runtime.h>
#include <cuda_bf16.h>
#include <cstdint>

#define D 128
#define DV 32          // D / 4 (float4)
#define EPS 1e-5f
#define NT 64          // nodes per MLP block
#define PA 136         // bf16 tile pitch (272B rows -> conflict-free LDSM)
#define PS 132         // f32 h2 tile pitch
#define MAXN 50000

// Device scratch (allocation-free rule: __device__ globals)
__device__ float4 g_agg4[(size_t)MAXN * DV];   // aggregated messages [N][D]
__device__ float4 g_hln4[(size_t)MAXN * DV];   // post-LayerNorm h    [N][D]
__device__ float  g_colsum[D];
__device__ float  g_colsumsq[D];
// Pre-packed weights in B-fragment register order:
// [kt(8)][nsub(16)][lane(32)] -> uint4{bhi0,bhi1,blo0,blo1}
__device__ uint4  g_w1p[4096];
__device__ uint4  g_w2p[4096];

// SMEM byte offsets for k_mlp
#define OFF_AHI 0
#define OFF_ALO 17408
#define OFF_HHI 34816
#define OFF_HLO 52224
#define SMEM_TOTAL 69632
// sS (64 x PS f32 = 33792 B) overlays [0, 34816)
// sPartS/sPartQ (4096 B each) overlay the H region after LN

// ---------------------------------------------------------------------------
// helpers
// ---------------------------------------------------------------------------
__device__ __forceinline__ uint32_t smem_u32(const void* p) {
    return (uint32_t)__cvta_generic_to_shared(p);
}

__device__ __forceinline__ void ldsm_x4(uint32_t* r, uint32_t addr) {
    asm volatile("ldmatrix.sync.aligned.m8n8.x4.shared.b16 {%0,%1,%2,%3}, [%4];"
                 : "=r"(r[0]), "=r"(r[1]), "=r"(r[2]), "=r"(r[3]) : "r"(addr));
}

__device__ __forceinline__ void mma16816(float* d, const uint32_t* a,
                                         const uint32_t* b) {
    asm volatile(
        "mma.sync.aligned.m16n8k16.row.col.f32.bf16.bf16.f32 "
        "{%0,%1,%2,%3}, {%4,%5,%6,%7}, {%8,%9}, {%0,%1,%2,%3};"
        : "+f"(d[0]), "+f"(d[1]), "+f"(d[2]), "+f"(d[3])
        : "r"(a[0]), "r"(a[1]), "r"(a[2]), "r"(a[3]), "r"(b[0]), "r"(b[1]));
}

__device__ __forceinline__ uint32_t bf2_hi(float a, float b, float& ra, float& rb) {
    __nv_bfloat16 ha = __float2bfloat16_rn(a);
    __nv_bfloat16 hb = __float2bfloat16_rn(b);
    ra = a - __bfloat162float(ha);
    rb = b - __bfloat162float(hb);
    __nv_bfloat162 h; h.x = ha; h.y = hb;
    return *(uint32_t*)&h;
}
__device__ __forceinline__ uint32_t bf2(float a, float b) {
    __nv_bfloat162 h; h.x = __float2bfloat16_rn(a); h.y = __float2bfloat16_rn(b);
    return *(uint32_t*)&h;
}

// ---------------------------------------------------------------------------
// K0: zero agg + stats accumulators
// ---------------------------------------------------------------------------
__global__ void k_zero(int total4) {
    int i = blockIdx.x * blockDim.x + threadIdx.x;
    if (i < total4) g_agg4[i] = make_float4(0.f, 0.f, 0.f, 0.f);
    if (i < D) { g_colsum[i] = 0.f; g_colsumsq[i] = 0.f; }
}

// ---------------------------------------------------------------------------
// K1: scatter-add messages (R3 proven form). edge_index is int32.
// ---------------------------------------------------------------------------
__global__ void k_scatter(const float* __restrict__ nh,
                          const float* __restrict__ eh,
                          const int* __restrict__ ei,
                          int E) {
    int gw   = (blockIdx.x * blockDim.x + threadIdx.x) >> 5;
    int lane = threadIdx.x & 31;
    if (gw >= E) return;
    int src = ei[gw];
    int dst = ei[E + gw];
    const float4* nh4 = (const float4*)(nh + (size_t)src * D);
    const float4* eh4 = (const float4*)(eh + (size_t)gw * D);
    float4 a = nh4[lane];
    float4 b = eh4[lane];
    float4 v = make_float4(a.x + b.x, a.y + b.y, a.z + b.z, a.w + b.w);
    float* p = (float*)(g_agg4 + (size_t)dst * DV) + lane * 4;
    asm volatile("red.global.add.v4.f32 [%0], {%1, %2, %3, %4};"
                 :: "l"(p), "f"(v.x), "f"(v.y), "f"(v.z), "f"(v.w)
                 : "memory");
}

// ---------------------------------------------------------------------------
// Kp: pack W1/W2 into bf16 hi/lo B-fragment order (4096 threads)
// ---------------------------------------------------------------------------
__global__ void k_prep(const float* __restrict__ w1, const float* __restrict__ w2) {
    int idx = blockIdx.x * blockDim.x + threadIdx.x;
    if (idx >= 4096) return;
    int lane = idx & 31;
    int nsub = (idx >> 5) & 15;
    int kt   = idx >> 9;
    int k0 = kt * 16 + (lane & 3) * 2;
    int n  = nsub * 8 + (lane >> 2);

    {
        float a0 = w1[(k0    ) * D + n], a1 = w1[(k0 + 1) * D + n];
        float a2 = w1[(k0 + 8) * D + n], a3 = w1[(k0 + 9) * D + n];
        float r0, r1, r2, r3;
        uint4 q;
        q.x = bf2_hi(a0, a1, r0, r1);
        q.y = bf2_hi(a2, a3, r2, r3);
        q.z = bf2(r0, r1);
        q.w = bf2(r2, r3);
        g_w1p[idx] = q;
    }
    {
        float a0 = w2[(k0    ) * D + n], a1 = w2[(k0 + 1) * D + n];
        float a2 = w2[(k0 + 8) * D + n], a3 = w2[(k0 + 9) * D + n];
        float r0, r1, r2, r3;
        uint4 q;
        q.x = bf2_hi(a0, a1, r0, r1);
        q.y = bf2_hi(a2, a3, r2, r3);
        q.z = bf2(r0, r1);
        q.w = bf2(r2, r3);
        g_w2p[idx] = q;
    }
}

// ---------------------------------------------------------------------------
// K2: tensor-core MLP, NT=64 nodes/block, 8 warps.
// Warp w: mh = w & 3 (16-row quarter), nq = w >> 2 (64-col half).
// Each warp computes a 16x64 output tile (acc[32], 8 B-frags per kt).
// ---------------------------------------------------------------------------
__global__ void k_mlp(const float* __restrict__ b1, const float* __restrict__ b2,
                      const float* __restrict__ lng, const float* __restrict__ lnb,
                      int N) {
    extern __shared__ char sb[];
    __nv_bfloat16* sAhi = (__nv_bfloat16*)(sb + OFF_AHI);
    float*         sS   = (float*)(sb);                 // overlays A region
    float*         sPartS = (float*)(sb + OFF_HHI);
    float*         sPartQ = (float*)(sb + OFF_HHI + 4096);

    const int t    = threadIdx.x;
    const int lane = t & 31;
    const int w    = t >> 5;
    const int nodeBase = blockIdx.x * NT;

    // ---- load agg tile (64 nodes), split to bf16 hi/lo ----
    {
        int n  = t >> 2;             // 0..63
        int k0 = (t & 3) * 32;       // 0,32,64,96
        int gn = nodeBase + n;
        __nv_bfloat16* rowHi = sAhi + n * PA;
        #pragma unroll
        for (int i = 0; i < 8; ++i) {
            float4 v = make_float4(0.f, 0.f, 0.f, 0.f);
            if (gn < N) v = g_agg4[(size_t)gn * DV + (k0 >> 2) + i];
            int kk = k0 + i * 4;
            float rx, ry, rz, rw;
            uint32_t h0 = bf2_hi(v.x, v.y, rx, ry);
            uint32_t h1 = bf2_hi(v.z, v.w, rz, rw);
            *(uint32_t*)((char*)(rowHi + kk))                       = h0;
            *(uint32_t*)((char*)(rowHi + kk + 2))                   = h1;
            *(uint32_t*)((char*)(rowHi + kk) + OFF_ALO)             = bf2(rx, ry);
            *(uint32_t*)((char*)(rowHi + kk + 2) + OFF_ALO)         = bf2(rz, rw);
        }
    }
    __syncthreads();

    const int mh = w & 3;            // row quarter (16 rows)
    const int nq = w >> 2;           // col half (64 cols = nsub 8*nq..8*nq+7)
    uint32_t aBase = smem_u32(sAhi + (mh * 16 + (lane & 15)) * PA) + (lane >> 4) * 16;

    float acc[32];
    #pragma unroll
    for (int i = 0; i < 32; ++i) acc[i] = 0.f;

    // ---- layer 1: h1 = relu(agg @ W1 + b1) ----
    #pragma unroll
    for (int kt = 0; kt < 8; ++kt) {
        uint32_t ah[4], al[4];
        ldsm_x4(ah, aBase + kt * 32);
        ldsm_x4(al, aBase + OFF_ALO + kt * 32);
        #pragma unroll
        for (int s = 0; s < 8; ++s) {
            uint4 q = g_w1p[(kt * 16 + nq * 8 + s) * 32 + lane];
            mma16816(acc + 4 * s, ah, &q.x);
            mma16816(acc + 4 * s, ah, &q.z);
            mma16816(acc + 4 * s, al, &q.x);
        }
    }
    #pragma unroll
    for (int s = 0; s < 8; ++s) {
        int cb = (nq * 8 + s) * 8 + (lane & 3) * 2;
        int r0 = mh * 16 + (lane >> 2);
        float2 bb = *(const float2*)(b1 + cb);
        float v00 = fmaxf(acc[4*s+0] + bb.x, 0.f);
        float v01 = fmaxf(acc[4*s+1] + bb.y, 0.f);
        float v10 = fmaxf(acc[4*s+2] + bb.x, 0.f);
        float v11 = fmaxf(acc[4*s+3] + bb.y, 0.f);
        float rx, ry;
        char* p0 = (char*)(sAhi + r0 * PA + cb) + OFF_HHI;
        char* p1 = (char*)(sAhi + (r0 + 8) * PA + cb) + OFF_HHI;
        uint32_t h;
        h = bf2_hi(v00, v01, rx, ry);
        *(uint32_t*)p0 = h; *(uint32_t*)(p0 + 17408) = bf2(rx, ry);
        h = bf2_hi(v10, v11, rx, ry);
        *(uint32_t*)p1 = h; *(uint32_t*)(p1 + 17408) = bf2(rx, ry);
    }
    __syncthreads();

    #pragma unroll
    for (int i = 0; i < 32; ++i) acc[i] = 0.f;

    // ---- layer 2: h2 = h1 @ W2 + b2 (reads H region; sS overlays A region) ----
    #pragma unroll
    for (int kt = 0; kt < 8; ++kt) {
        uint32_t ah[4], al[4];
        ldsm_x4(ah, aBase + OFF_HHI + kt * 32);
        ldsm_x4(al, aBase + OFF_HLO + kt * 32);
        #pragma unroll
        for (int s = 0; s < 8; ++s) {
            uint4 q = g_w2p[(kt * 16 + nq * 8 + s) * 32 + lane];
            mma16816(acc + 4 * s, ah, &q.x);
            mma16816(acc + 4 * s, ah, &q.z);
            mma16816(acc + 4 * s, al, &q.x);
        }
    }
    // A region is dead (all layer-1 reads completed before the sync above),
    // safe to overwrite with sS now.
    #pragma unroll
    for (int s = 0; s < 8; ++s) {
        int cb = (nq * 8 + s) * 8 + (lane & 3) * 2;
        int r0 = mh * 16 + (lane >> 2);
        float2 bb = *(const float2*)(b2 + cb);
        *(float2*)(sS + r0 * PS + cb)       = make_float2(acc[4*s+0] + bb.x, acc[4*s+1] + bb.y);
        *(float2*)(sS + (r0 + 8) * PS + cb) = make_float2(acc[4*s+2] + bb.x, acc[4*s+3] + bb.y);
    }
    __syncthreads();

    // ---- LayerNorm per node (warp per node, 8 nodes/warp) + column partials ----
    float colS[4] = {0.f, 0.f, 0.f, 0.f};
    float colQ[4] = {0.f, 0.f, 0.f, 0.f};

    #pragma unroll
    for (int r = 0; r < 8; ++r) {
        int n  = w + r * 8;          // 0..63
        int gn = nodeBase + n;
        float v0 = sS[n * PS + lane];
        float v1 = sS[n * PS + lane + 32];
        float v2 = sS[n * PS + lane + 64];
        float v3 = sS[n * PS + lane + 96];
        float s = v0 + v1 + v2 + v3;
        float q = v0*v0 + v1*v1 + v2*v2 + v3*v3;
        #pragma unroll
        for (int o = 16; o; o >>= 1) {
            s += __shfl_xor_sync(0xFFFFFFFFu, s, o);
            q += __shfl_xor_sync(0xFFFFFFFFu, q, o);
        }
        float mu  = s * (1.f / 128.f);
        float var = q * (1.f / 128.f) - mu * mu;
        float inv = rsqrtf(var + EPS);
        if (gn < N) {
            float y0 = (v0 - mu) * inv * lng[lane]      + lnb[lane];
            float y1 = (v1 - mu) * inv * lng[lane + 32] + lnb[lane + 32];
            float y2 = (v2 - mu) * inv * lng[lane + 64] + lnb[lane + 64];
            float y3 = (v3 - mu) * inv * lng[lane + 96] + lnb[lane + 96];
            float* hp = (float*)(g_hln4 + (size_t)gn * DV);
            hp[lane]      = y0;
            hp[lane + 32] = y1;
            hp[lane + 64] = y2;
            hp[lane + 96] = y3;
            colS[0] += y0; colQ[0] += y0 * y0;
            colS[1] += y1; colQ[1] += y1 * y1;
            colS[2] += y2; colQ[2] += y2 * y2;
            colS[3] += y3; colQ[3] += y3 * y3;
        }
    }
    __syncthreads();                 // H region dead -> reuse as partials
    #pragma unroll
    for (int qq = 0; qq < 4; ++qq) {
        sPartS[w * D + lane + 32 * qq] = colS[qq];
        sPartQ[w * D + lane + 32 * qq] = colQ[qq];
    }
    __syncthreads();
    if (t < D) {
        float s = 0.f, q = 0.f;
        #pragma unroll
        for (int w8 = 0; w8 < 8; ++w8) {
            s += sPartS[w8 * D + t];
            q += sPartQ[w8 * D + t];
        }
        atomicAdd(&g_colsum[t], s);
        atomicAdd(&g_colsumsq[t], q);
    }
}

// ---------------------------------------------------------------------------
// K4: out = relu((hln - ms*gmu) * mul + gn_b) + node_hidden
// GraphNorm finalize is recomputed per block from L2-resident accumulators
// (removes the separate k_statfin launch).
// ---------------------------------------------------------------------------
__global__ void k_final(const float* __restrict__ nh,
                        const float* __restrict__ gnw,
                        const float* __restrict__ gnb,
                        const float* __restrict__ gnms,
                        float invN,
                        float* __restrict__ out,
                        int total4) {
    __shared__ float sMul[D], sSub[D], sB[D];
    int t = threadIdx.x;
    if (t < D) {
        float gmu = g_colsum[t] * invN;
        float e2  = g_colsumsq[t] * invN;
        float ms  = gnms[t];
        float gvar = e2 - 2.f * ms * gmu * gmu + ms * ms * gmu * gmu;
        sMul[t] = rsqrtf(gvar + EPS) * gnw[t];
        sSub[t] = ms * gmu;
        sB[t]   = gnb[t];
    }
    __syncthreads();
    int i = blockIdx.x * blockDim.x + t;
    if (i >= total4) return;
    int c4 = (i & (DV - 1)) * 4;
    float4 h = g_hln4[i];
    float4 x = ((const float4*)nh)[i];
    float4 o;
    o.x = fmaxf((h.x - sSub[c4 + 0]) * sMul[c4 + 0] + sB[c4 + 0], 0.f) + x.x;
    o.y = fmaxf((h.y - sSub[c4 + 1]) * sMul[c4 + 1] + sB[c4 + 1], 0.f) + x.y;
    o.z = fmaxf((h.z - sSub[c4 + 2]) * sMul[c4 + 2] + sB[c4 + 2], 0.f) + x.z;
    o.w = fmaxf((h.w - sSub[c4 + 3]) * sMul[c4 + 3] + sB[c4 + 3], 0.f) + x.w;
    ((float4*)out)[i] = o;
}

// ---------------------------------------------------------------------------
extern "C" void kernel_launch(void* const* d_in, const int* in_sizes, int n_in,
                              void* d_out, int out_size) {
    const float* nh   = (const float*)d_in[0];
    const float* eh   = (const float*)d_in[1];
    const float* w1   = (const float*)d_in[2];
    const float* b1   = (const float*)d_in[3];
    const float* w2   = (const float*)d_in[4];
    const float* b2   = (const float*)d_in[5];
    const float* lng  = (const float*)d_in[6];
    const float* lnb  = (const float*)d_in[7];
    const float* gnw  = (const float*)d_in[8];
    const float* gnb  = (const float*)d_in[9];
    const float* gnms = (const float*)d_in[10];
    const int*   ei   = (const int*)d_in[11];

    int N = in_sizes[0] / D;
    int E = in_sizes[1] / D;
    int total4 = N * DV;

    cudaFuncSetAttribute(k_mlp, cudaFuncAttributeMaxDynamicSharedMemorySize, SMEM_TOTAL);

    k_zero<<<(total4 + 255) / 256, 256>>>(total4);
    k_prep<<<16, 256>>>(w1, w2);
    k_scatter<<<(E + 7) / 8, 256>>>(nh, eh, ei, E);
    k_mlp<<<(N + NT - 1) / NT, 256, SMEM_TOTAL>>>(b1, b2, lng, lnb, N);
    k_final<<<(total4 + 255) / 256, 256>>>(nh, gnw, gnb, gnms, 1.f / (float)N,
                                           (float*)d_out, total4);
}

// round 6
// speedup vs baseline: 1.3886x; 1.0742x over previous
#include <cuda_runtime.h>
#include <cuda_bf16.h>
#include <cstdint>

#define D 128
#define DV 32          // D / 4 (float4)
#define EPS 1e-5f
#define NT 64          // nodes per MLP block
#define PA 136         // bf16 tile pitch (272B rows -> conflict-free LDSM)
#define PS 132         // f32 h2 tile pitch
#define MAXN 50000

// Device scratch (allocation-free rule: __device__ globals)
__device__ float4 g_agg4[(size_t)MAXN * DV];   // aggregated messages [N][D]
__device__ float4 g_hln4[(size_t)MAXN * DV];   // post-LayerNorm h    [N][D]
__device__ float  g_colsum[D];
__device__ float  g_colsumsq[D];
// Pre-packed weights in B-fragment register order:
// [kt(8)][nsub(16)][lane(32)] -> uint4{bhi0,bhi1,blo0,blo1}
__device__ uint4  g_w1p[4096];
__device__ uint4  g_w2p[4096];

// SMEM layout for k_mlp (A region reused for H, then sS, then partials)
#define OFF_ALO 17408            // hi at 0, lo at 17408
#define SMEM_TOTAL 34816

// ---------------------------------------------------------------------------
// helpers
// ---------------------------------------------------------------------------
__device__ __forceinline__ uint32_t smem_u32(const void* p) {
    return (uint32_t)__cvta_generic_to_shared(p);
}

__device__ __forceinline__ void ldsm_x4(uint32_t* r, uint32_t addr) {
    asm volatile("ldmatrix.sync.aligned.m8n8.x4.shared.b16 {%0,%1,%2,%3}, [%4];"
                 : "=r"(r[0]), "=r"(r[1]), "=r"(r[2]), "=r"(r[3]) : "r"(addr));
}

__device__ __forceinline__ void mma16816(float* d, const uint32_t* a,
                                         const uint32_t* b) {
    asm volatile(
        "mma.sync.aligned.m16n8k16.row.col.f32.bf16.bf16.f32 "
        "{%0,%1,%2,%3}, {%4,%5,%6,%7}, {%8,%9}, {%0,%1,%2,%3};"
        : "+f"(d[0]), "+f"(d[1]), "+f"(d[2]), "+f"(d[3])
        : "r"(a[0]), "r"(a[1]), "r"(a[2]), "r"(a[3]), "r"(b[0]), "r"(b[1]));
}

__device__ __forceinline__ uint32_t bf2_hi(float a, float b, float& ra, float& rb) {
    __nv_bfloat16 ha = __float2bfloat16_rn(a);
    __nv_bfloat16 hb = __float2bfloat16_rn(b);
    ra = a - __bfloat162float(ha);
    rb = b - __bfloat162float(hb);
    __nv_bfloat162 h; h.x = ha; h.y = hb;
    return *(uint32_t*)&h;
}
__device__ __forceinline__ uint32_t bf2(float a, float b) {
    __nv_bfloat162 h; h.x = __float2bfloat16_rn(a); h.y = __float2bfloat16_rn(b);
    return *(uint32_t*)&h;
}

// ---------------------------------------------------------------------------
// K0: zero agg + stats accumulators
// ---------------------------------------------------------------------------
__global__ void k_zero(int total4) {
    int i = blockIdx.x * blockDim.x + threadIdx.x;
    if (i < total4) g_agg4[i] = make_float4(0.f, 0.f, 0.f, 0.f);
    if (i < D) { g_colsum[i] = 0.f; g_colsumsq[i] = 0.f; }
}

// ---------------------------------------------------------------------------
// K1: scatter-add messages (proven R3 form). edge_index is int32.
// ---------------------------------------------------------------------------
__global__ void k_scatter(const float* __restrict__ nh,
                          const float* __restrict__ eh,
                          const int* __restrict__ ei,
                          int E) {
    int gw   = (blockIdx.x * blockDim.x + threadIdx.x) >> 5;
    int lane = threadIdx.x & 31;
    if (gw >= E) return;
    int src = ei[gw];
    int dst = ei[E + gw];
    const float4* nh4 = (const float4*)(nh + (size_t)src * D);
    const float4* eh4 = (const float4*)(eh + (size_t)gw * D);
    float4 a = nh4[lane];
    float4 b = eh4[lane];
    float4 v = make_float4(a.x + b.x, a.y + b.y, a.z + b.z, a.w + b.w);
    float* p = (float*)(g_agg4 + (size_t)dst * DV) + lane * 4;
    asm volatile("red.global.add.v4.f32 [%0], {%1, %2, %3, %4};"
                 :: "l"(p), "f"(v.x), "f"(v.y), "f"(v.z), "f"(v.w)
                 : "memory");
}

// ---------------------------------------------------------------------------
// Kp: pack W1/W2 into bf16 hi/lo B-fragment order (4096 threads)
// ---------------------------------------------------------------------------
__global__ void k_prep(const float* __restrict__ w1, const float* __restrict__ w2) {
    int idx = blockIdx.x * blockDim.x + threadIdx.x;
    if (idx >= 4096) return;
    int lane = idx & 31;
    int nsub = (idx >> 5) & 15;
    int kt   = idx >> 9;
    int k0 = kt * 16 + (lane & 3) * 2;
    int n  = nsub * 8 + (lane >> 2);

    {
        float a0 = w1[(k0    ) * D + n], a1 = w1[(k0 + 1) * D + n];
        float a2 = w1[(k0 + 8) * D + n], a3 = w1[(k0 + 9) * D + n];
        float r0, r1, r2, r3;
        uint4 q;
        q.x = bf2_hi(a0, a1, r0, r1);
        q.y = bf2_hi(a2, a3, r2, r3);
        q.z = bf2(r0, r1);
        q.w = bf2(r2, r3);
        g_w1p[idx] = q;
    }
    {
        float a0 = w2[(k0    ) * D + n], a1 = w2[(k0 + 1) * D + n];
        float a2 = w2[(k0 + 8) * D + n], a3 = w2[(k0 + 9) * D + n];
        float r0, r1, r2, r3;
        uint4 q;
        q.x = bf2_hi(a0, a1, r0, r1);
        q.y = bf2_hi(a2, a3, r2, r3);
        q.z = bf2(r0, r1);
        q.w = bf2(r2, r3);
        g_w2p[idx] = q;
    }
}

// ---------------------------------------------------------------------------
// K2: tensor-core MLP, NT=64 nodes/block, 8 warps.
// Warp w: mh = w & 1 (32-row half), nq = w >> 1 (32-col quarter).
// Warp tile: m32 x n32 (acc[2][16]); each weight fragment loaded by only
// 2 warps per 64 nodes -> 4KB/node weight traffic (half of R3).
// A region (hi/lo, 34816 B) is sequentially reused: A -> H -> sS -> partials,
// with accumulators held in registers across the overwrite syncs.
// ---------------------------------------------------------------------------
__global__ void k_mlp(const float* __restrict__ b1, const float* __restrict__ b2,
                      const float* __restrict__ lng, const float* __restrict__ lnb,
                      int N) {
    extern __shared__ char sb[];
    __nv_bfloat16* sHi = (__nv_bfloat16*)(sb);
    float*         sS  = (float*)(sb);
    float*         sPartS = (float*)(sb);
    float*         sPartQ = (float*)(sb + 4096);

    const int t    = threadIdx.x;
    const int lane = t & 31;
    const int w    = t >> 5;
    const int nodeBase = blockIdx.x * NT;

    // ---- load agg tile (64 nodes), split to bf16 hi/lo ----
    {
        int n  = t >> 2;             // 0..63
        int k0 = (t & 3) * 32;       // 0,32,64,96
        int gn = nodeBase + n;
        __nv_bfloat16* rowHi = sHi + n * PA;
        #pragma unroll
        for (int i = 0; i < 8; ++i) {
            float4 v = make_float4(0.f, 0.f, 0.f, 0.f);
            if (gn < N) v = g_agg4[(size_t)gn * DV + (k0 >> 2) + i];
            int kk = k0 + i * 4;
            float rx, ry, rz, rw;
            uint32_t h0 = bf2_hi(v.x, v.y, rx, ry);
            uint32_t h1 = bf2_hi(v.z, v.w, rz, rw);
            *(uint32_t*)((char*)(rowHi + kk))               = h0;
            *(uint32_t*)((char*)(rowHi + kk + 2))           = h1;
            *(uint32_t*)((char*)(rowHi + kk) + OFF_ALO)     = bf2(rx, ry);
            *(uint32_t*)((char*)(rowHi + kk + 2) + OFF_ALO) = bf2(rz, rw);
        }
    }
    __syncthreads();

    const int mh = w & 1;            // 32-row half
    const int nq = w >> 1;           // 32-col quarter
    // ldsm bases for the two 16-row m-tiles of this warp
    const uint32_t aB0 = smem_u32(sHi + (mh * 32 + (lane & 15)) * PA) + (lane >> 4) * 16;
    const uint32_t aB1 = aB0 + 16 * PA * 2;   // +16 rows

    float acc[32];
    #pragma unroll
    for (int i = 0; i < 32; ++i) acc[i] = 0.f;

    // ---- layer 1: h1 = relu(agg @ W1 + b1) ----
    #pragma unroll
    for (int kt = 0; kt < 8; ++kt) {
        uint32_t a0h[4], a0l[4], a1h[4], a1l[4];
        ldsm_x4(a0h, aB0 + kt * 32);
        ldsm_x4(a0l, aB0 + OFF_ALO + kt * 32);
        ldsm_x4(a1h, aB1 + kt * 32);
        ldsm_x4(a1l, aB1 + OFF_ALO + kt * 32);
        #pragma unroll
        for (int s = 0; s < 4; ++s) {
            uint4 q = g_w1p[(kt * 16 + nq * 4 + s) * 32 + lane];
            mma16816(acc + 4 * s,      a0h, &q.x);
            mma16816(acc + 4 * s,      a0h, &q.z);
            mma16816(acc + 4 * s,      a0l, &q.x);
            mma16816(acc + 16 + 4 * s, a1h, &q.x);
            mma16816(acc + 16 + 4 * s, a1h, &q.z);
            mma16816(acc + 16 + 4 * s, a1l, &q.x);
        }
    }
    __syncthreads();                 // everyone done reading A -> overwrite with H
    #pragma unroll
    for (int m = 0; m < 2; ++m) {
        #pragma unroll
        for (int s = 0; s < 4; ++s) {
            int cb = nq * 32 + s * 8 + (lane & 3) * 2;
            int r0 = mh * 32 + m * 16 + (lane >> 2);
            float2 bb = *(const float2*)(b1 + cb);
            float v00 = fmaxf(acc[16*m + 4*s + 0] + bb.x, 0.f);
            float v01 = fmaxf(acc[16*m + 4*s + 1] + bb.y, 0.f);
            float v10 = fmaxf(acc[16*m + 4*s + 2] + bb.x, 0.f);
            float v11 = fmaxf(acc[16*m + 4*s + 3] + bb.y, 0.f);
            float rx, ry;
            char* p0 = (char*)(sHi + r0 * PA + cb);
            char* p1 = (char*)(sHi + (r0 + 8) * PA + cb);
            uint32_t h;
            h = bf2_hi(v00, v01, rx, ry);
            *(uint32_t*)p0 = h; *(uint32_t*)(p0 + OFF_ALO) = bf2(rx, ry);
            h = bf2_hi(v10, v11, rx, ry);
            *(uint32_t*)p1 = h; *(uint32_t*)(p1 + OFF_ALO) = bf2(rx, ry);
        }
    }
    __syncthreads();

    #pragma unroll
    for (int i = 0; i < 32; ++i) acc[i] = 0.f;

    // ---- layer 2: h2 = h1 @ W2 + b2 (H lives in the A region) ----
    #pragma unroll
    for (int kt = 0; kt < 8; ++kt) {
        uint32_t a0h[4], a0l[4], a1h[4], a1l[4];
        ldsm_x4(a0h, aB0 + kt * 32);
        ldsm_x4(a0l, aB0 + OFF_ALO + kt * 32);
        ldsm_x4(a1h, aB1 + kt * 32);
        ldsm_x4(a1l, aB1 + OFF_ALO + kt * 32);
        #pragma unroll
        for (int s = 0; s < 4; ++s) {
            uint4 q = g_w2p[(kt * 16 + nq * 4 + s) * 32 + lane];
            mma16816(acc + 4 * s,      a0h, &q.x);
            mma16816(acc + 4 * s,      a0h, &q.z);
            mma16816(acc + 4 * s,      a0l, &q.x);
            mma16816(acc + 16 + 4 * s, a1h, &q.x);
            mma16816(acc + 16 + 4 * s, a1h, &q.z);
            mma16816(acc + 16 + 4 * s, a1l, &q.x);
        }
    }
    __syncthreads();                 // H dead -> overwrite with sS
    #pragma unroll
    for (int m = 0; m < 2; ++m) {
        #pragma unroll
        for (int s = 0; s < 4; ++s) {
            int cb = nq * 32 + s * 8 + (lane & 3) * 2;
            int r0 = mh * 32 + m * 16 + (lane >> 2);
            float2 bb = *(const float2*)(b2 + cb);
            *(float2*)(sS + r0 * PS + cb)       = make_float2(acc[16*m + 4*s + 0] + bb.x,
                                                              acc[16*m + 4*s + 1] + bb.y);
            *(float2*)(sS + (r0 + 8) * PS + cb) = make_float2(acc[16*m + 4*s + 2] + bb.x,
                                                              acc[16*m + 4*s + 3] + bb.y);
        }
    }
    __syncthreads();

    // ---- LayerNorm per node (warp per node, 8 nodes/warp) + column partials ----
    float colS[4] = {0.f, 0.f, 0.f, 0.f};
    float colQ[4] = {0.f, 0.f, 0.f, 0.f};

    #pragma unroll
    for (int r = 0; r < 8; ++r) {
        int n  = w + r * 8;          // 0..63
        int gn = nodeBase + n;
        float v0 = sS[n * PS + lane];
        float v1 = sS[n * PS + lane + 32];
        float v2 = sS[n * PS + lane + 64];
        float v3 = sS[n * PS + lane + 96];
        float s = v0 + v1 + v2 + v3;
        float q = v0*v0 + v1*v1 + v2*v2 + v3*v3;
        #pragma unroll
        for (int o = 16; o; o >>= 1) {
            s += __shfl_xor_sync(0xFFFFFFFFu, s, o);
            q += __shfl_xor_sync(0xFFFFFFFFu, q, o);
        }
        float mu  = s * (1.f / 128.f);
        float var = q * (1.f / 128.f) - mu * mu;
        float inv = rsqrtf(var + EPS);
        if (gn < N) {
            float y0 = (v0 - mu) * inv * lng[lane]      + lnb[lane];
            float y1 = (v1 - mu) * inv * lng[lane + 32] + lnb[lane + 32];
            float y2 = (v2 - mu) * inv * lng[lane + 64] + lnb[lane + 64];
            float y3 = (v3 - mu) * inv * lng[lane + 96] + lnb[lane + 96];
            float* hp = (float*)(g_hln4 + (size_t)gn * DV);
            hp[lane]      = y0;
            hp[lane + 32] = y1;
            hp[lane + 64] = y2;
            hp[lane + 96] = y3;
            colS[0] += y0; colQ[0] += y0 * y0;
            colS[1] += y1; colQ[1] += y1 * y1;
            colS[2] += y2; colQ[2] += y2 * y2;
            colS[3] += y3; colQ[3] += y3 * y3;
        }
    }
    __syncthreads();                 // sS dead -> partials
    #pragma unroll
    for (int qq = 0; qq < 4; ++qq) {
        sPartS[w * D + lane + 32 * qq] = colS[qq];
        sPartQ[w * D + lane + 32 * qq] = colQ[qq];
    }
    __syncthreads();
    if (t < D) {
        float s = 0.f, q = 0.f;
        #pragma unroll
        for (int w8 = 0; w8 < 8; ++w8) {
            s += sPartS[w8 * D + t];
            q += sPartQ[w8 * D + t];
        }
        atomicAdd(&g_colsum[t], s);
        atomicAdd(&g_colsumsq[t], q);
    }
}

// ---------------------------------------------------------------------------
// K4: out = relu((hln - ms*gmu) * mul + gn_b) + node_hidden
// GraphNorm finalize recomputed per block from L2-resident accumulators.
// ---------------------------------------------------------------------------
__global__ void k_final(const float* __restrict__ nh,
                        const float* __restrict__ gnw,
                        const float* __restrict__ gnb,
                        const float* __restrict__ gnms,
                        float invN,
                        float* __restrict__ out,
                        int total4) {
    __shared__ float sMul[D], sSub[D], sB[D];
    int t = threadIdx.x;
    if (t < D) {
        float gmu = g_colsum[t] * invN;
        float e2  = g_colsumsq[t] * invN;
        float ms  = gnms[t];
        float gvar = e2 - 2.f * ms * gmu * gmu + ms * ms * gmu * gmu;
        sMul[t] = rsqrtf(gvar + EPS) * gnw[t];
        sSub[t] = ms * gmu;
        sB[t]   = gnb[t];
    }
    __syncthreads();
    int i = blockIdx.x * blockDim.x + t;
    if (i >= total4) return;
    int c4 = (i & (DV - 1)) * 4;
    float4 h = g_hln4[i];
    float4 x = ((const float4*)nh)[i];
    float4 o;
    o.x = fmaxf((h.x - sSub[c4 + 0]) * sMul[c4 + 0] + sB[c4 + 0], 0.f) + x.x;
    o.y = fmaxf((h.y - sSub[c4 + 1]) * sMul[c4 + 1] + sB[c4 + 1], 0.f) + x.y;
    o.z = fmaxf((h.z - sSub[c4 + 2]) * sMul[c4 + 2] + sB[c4 + 2], 0.f) + x.z;
    o.w = fmaxf((h.w - sSub[c4 + 3]) * sMul[c4 + 3] + sB[c4 + 3], 0.f) + x.w;
    ((float4*)out)[i] = o;
}

// ---------------------------------------------------------------------------
extern "C" void kernel_launch(void* const* d_in, const int* in_sizes, int n_in,
                              void* d_out, int out_size) {
    const float* nh   = (const float*)d_in[0];
    const float* eh   = (const float*)d_in[1];
    const float* w1   = (const float*)d_in[2];
    const float* b1   = (const float*)d_in[3];
    const float* w2   = (const float*)d_in[4];
    const float* b2   = (const float*)d_in[5];
    const float* lng  = (const float*)d_in[6];
    const float* lnb  = (const float*)d_in[7];
    const float* gnw  = (const float*)d_in[8];
    const float* gnb  = (const float*)d_in[9];
    const float* gnms = (const float*)d_in[10];
    const int*   ei   = (const int*)d_in[11];

    int N = in_sizes[0] / D;
    int E = in_sizes[1] / D;
    int total4 = N * DV;

    cudaFuncSetAttribute(k_mlp, cudaFuncAttributeMaxDynamicSharedMemorySize, SMEM_TOTAL);

    k_zero<<<(total4 + 255) / 256, 256>>>(total4);
    k_prep<<<16, 256>>>(w1, w2);
    k_scatter<<<(E + 7) / 8, 256>>>(nh, eh, ei, E);
    k_mlp<<<(N + NT - 1) / NT, 256, SMEM_TOTAL>>>(b1, b2, lng, lnb, N);
    k_final<<<(total4 + 255) / 256, 256>>>(nh, gnw, gnb, gnms, 1.f / (float)N,
                                           (float*)d_out, total4);
}